// round 6
// baseline (speedup 1.0000x reference)
#include <cuda_runtime.h>
#include <cuda_fp16.h>
#include <cstdint>

// Problem constants (fixed shapes)
#define BB 8
#define GG 64
#define CC 192
#define HWN 65536          // H*W
#define OO 256             // width2

#define WPITCH 72          // fp16 elements per row (144B): conflict-free ldmatrix

#define N_ATTN_ITEMS 512
#define N_FUSED_ITEMS 8192
#define GRID_MEGA 296

// ---------------------------------------------------------------------------
// Device scratch
// ---------------------------------------------------------------------------
__device__ float4 g_attnW[BB * GG];
__device__ __align__(16) __half g_Whalf[OO * WPITCH];
__device__ float2 g_bn2[OO];
__device__ unsigned g_ready[BB];
__device__ unsigned g_qa;          // attn work queue
__device__ unsigned g_qf;          // fused work queue

__device__ __forceinline__ uint32_t smem_u32(const void* p) {
    uint32_t a;
    asm("{ .reg .u64 t; cvta.to.shared.u64 t, %1; cvt.u32.u64 %0, t; }" : "=r"(a) : "l"(p));
    return a;
}
__device__ __forceinline__ void ldmat_x4(uint32_t* r, uint32_t addr) {
    asm volatile("ldmatrix.sync.aligned.m8n8.x4.shared.b16 {%0,%1,%2,%3}, [%4];"
                 : "=r"(r[0]), "=r"(r[1]), "=r"(r[2]), "=r"(r[3]) : "r"(addr));
}
__device__ __forceinline__ void ldmat_x2(uint32_t* r, uint32_t addr) {
    asm volatile("ldmatrix.sync.aligned.m8n8.x2.shared.b16 {%0,%1}, [%2];"
                 : "=r"(r[0]), "=r"(r[1]) : "r"(addr));
}
__device__ __forceinline__ void mma_16816(float* d, const uint32_t* a, const uint32_t* b) {
    asm volatile("mma.sync.aligned.m16n8k16.row.col.f32.f16.f16.f32 "
                 "{%0,%1,%2,%3}, {%4,%5,%6,%7}, {%8,%9}, {%0,%1,%2,%3};"
                 : "+f"(d[0]), "+f"(d[1]), "+f"(d[2]), "+f"(d[3])
                 : "r"(a[0]), "r"(a[1]), "r"(a[2]), "r"(a[3]), "r"(b[0]), "r"(b[1]));
}

// ---------------------------------------------------------------------------
// Kernel 0: prep — conv_w -> fp16 pitched tile, fold bn2, reset flags/queues.
// ---------------------------------------------------------------------------
__global__ __launch_bounds__(256) void prep_kernel(
    const float* __restrict__ convw,
    const float* __restrict__ bn2_g, const float* __restrict__ bn2_b,
    const float* __restrict__ bn2_m, const float* __restrict__ bn2_v)
{
    const int i = blockIdx.x * 256 + threadIdx.x;   // 0..16383
    const int k = i & 63;
    const int o = i >> 6;
    g_Whalf[o * WPITCH + k] = __float2half(convw[o * GG + k]);
    if (i < OO) {
#pragma unroll
        for (int z = 64; z < WPITCH; z++)
            g_Whalf[i * WPITCH + z] = __float2half(0.f);
        float sc = bn2_g[i] * rsqrtf(bn2_v[i] + 1e-5f);
        float bi = bn2_b[i] - sc * bn2_m[i];
        g_bn2[i] = make_float2(sc, bi);
    }
    if (i < BB) g_ready[i] = 0;
    if (i == 0) { g_qa = 0; g_qf = 0; }
}

// ---------------------------------------------------------------------------
// Attn item: one (b,g). 256 threads. Streams 3 channels, pooled Gram,
// collapse + softmax + bn1 fold -> g_attnW, then release g_ready[b].
// ---------------------------------------------------------------------------
__device__ void do_attn_item(
    int bg, const float* __restrict__ x,
    const float* __restrict__ aw,
    const float* __restrict__ bn1_g, const float* __restrict__ bn1_b,
    const float* __restrict__ bn1_m, const float* __restrict__ bn1_v,
    float (*red)[8], float* fin)
{
    const int g  = bg & 63;
    const float* xb = x + (size_t)bg * 3 * HWN;
    const int t    = threadIdx.x;
    const int lane = t & 31;
    const int warp = t >> 5;

    float acc[9];
#pragma unroll
    for (int q = 0; q < 9; q++) acc[q] = 0.0f;

#pragma unroll 1
    for (int it = 0; it < 16; it++) {
        const int wIdx = it * 256 + t;
        const int wy = wIdx >> 6;
        const int wx = wIdx & 63;
        float m[3], s[3];
#pragma unroll
        for (int ch = 0; ch < 3; ch++) {
            const float4* pc = (const float4*)(xb + (size_t)ch * HWN + (wy * 4) * 256 + wx * 4);
            float4 r0 = __ldcs(pc);
            float4 r1 = __ldcs(pc + 64);
            float4 r2 = __ldcs(pc + 128);
            float4 r3 = __ldcs(pc + 192);
            float mx = fmaxf(fmaxf(fmaxf(r0.x, r0.y), fmaxf(r0.z, r0.w)),
                      fmaxf(fmaxf(fmaxf(r1.x, r1.y), fmaxf(r1.z, r1.w)),
                      fmaxf(fmaxf(fmaxf(r2.x, r2.y), fmaxf(r2.z, r2.w)),
                            fmaxf(fmaxf(r3.x, r3.y), fmaxf(r3.z, r3.w)))));
            float sm = (r0.x + r0.y + r0.z + r0.w) + (r1.x + r1.y + r1.z + r1.w)
                     + (r2.x + r2.y + r2.z + r2.w) + (r3.x + r3.y + r3.z + r3.w);
            m[ch] = mx;
            s[ch] = sm;
        }
#pragma unroll
        for (int i = 0; i < 3; i++)
#pragma unroll
            for (int j = 0; j < 3; j++)
                acc[i * 3 + j] += m[i] * s[j];
    }

#pragma unroll
    for (int q = 0; q < 9; q++) {
        float v = acc[q];
#pragma unroll
        for (int off = 16; off > 0; off >>= 1)
            v += __shfl_xor_sync(0xFFFFFFFFu, v, off);
        if (lane == 0) red[q][warp] = v;
    }
    __syncthreads();
    if (t < 9) {
        float s = 0.0f;
#pragma unroll
        for (int w = 0; w < 8; w++) s += red[t][w];
        fin[t] = s;
    }
    __syncthreads();

    if (t == 0) {
        const float w0 = aw[g * 3 + 0], w1 = aw[g * 3 + 1], w2 = aw[g * 3 + 2];
        float r0 = (fin[0] * w0 + fin[3] * w1 + fin[6] * w2) * (1.0f / 1024.0f);
        float r1 = (fin[1] * w0 + fin[4] * w1 + fin[7] * w2) * (1.0f / 1024.0f);
        float r2 = (fin[2] * w0 + fin[5] * w1 + fin[8] * w2) * (1.0f / 1024.0f);
        float mx = fmaxf(r0, fmaxf(r1, r2));
        float e0 = __expf(r0 - mx), e1 = __expf(r1 - mx), e2 = __expf(r2 - mx);
        float inv = 1.0f / (e0 + e1 + e2);
        float sc = bn1_g[g] * rsqrtf(bn1_v[g] + 1e-5f);
        float cc = bn1_b[g] - sc * bn1_m[g];
        float4 o;
        o.x = sc * e0 * inv;
        o.y = sc * e1 * inv;
        o.z = sc * e2 * inv;
        o.w = cc;
        g_attnW[bg] = o;
        __threadfence();
        atomicAdd(&g_ready[bg >> 6], 1u);
    }
}

// ---------------------------------------------------------------------------
// Fused item: one (b, n0) 256o x 64n tile. Phase A -> Ysm fp16; HMMA GEMM; bn2.
// ---------------------------------------------------------------------------
__device__ void do_fused_item(
    int idx, const float* __restrict__ x, float* __restrict__ out,
    __half* Wsm, __half* Ysm)
{
    const int b  = idx >> 10;
    const int n0 = (idx & 1023) << 6;
    const int t    = threadIdx.x;
    const int lane = t & 31;
    const int wid  = t >> 5;

    // wait for this batch's attention weights
    if (t == 0) {
        while (atomicAdd(&g_ready[b], 0u) < 64u) __nanosleep(128);
    }
    __syncthreads();

    // ---- Phase A: Y = relu(bn1(sum_j a_j x_j)) -> fp16 smem [n][k] ----
    {
        const int pos = t & 63;
        const int gq  = t >> 6;                       // 0..3
        const float* xb = x + (size_t)b * CC * HWN + n0 + pos;
        const float4* awb = g_attnW + b * GG;
        __half* yrow = Ysm + pos * WPITCH;
#pragma unroll
        for (int it = 0; it < 16; it++) {
            const int g = it * 4 + gq;
            const float4 a = __ldcg(awb + g);         // L2-coherent (intra-kernel producer)
            const float* p = xb + (size_t)(g * 3) * HWN;
            float x0 = __ldcs(p);
            float x1 = __ldcs(p + HWN);
            float x2 = __ldcs(p + 2 * HWN);
            float y = fmaf(a.x, x0, fmaf(a.y, x1, fmaf(a.z, x2, a.w)));
            yrow[g] = __float2half(fmaxf(y, 0.0f));
        }
    }
    __syncthreads();

    // ---- Phase B: HMMA GEMM. warp tile: o in [ow, ow+64), n in [nw, nw+32) ----
    const int ow = (wid >> 1) * 64;
    const int nw = (wid & 1) * 32;

    float acc[4][4][4];
#pragma unroll
    for (int m = 0; m < 4; m++)
#pragma unroll
        for (int j = 0; j < 4; j++)
#pragma unroll
            for (int q = 0; q < 4; q++) acc[m][j][q] = 0.0f;

    const uint32_t wbase = smem_u32(Wsm);
    const uint32_t ybase = smem_u32(Ysm);
    const uint32_t aAddr = wbase + (ow + (lane & 15)) * (WPITCH * 2) + ((lane >> 4) * 8) * 2;
    const uint32_t bAddr = ybase + (nw + (lane & 7)) * (WPITCH * 2) + (((lane >> 3) & 1) * 8) * 2;

#pragma unroll
    for (int k0 = 0; k0 < 64; k0 += 16) {
        uint32_t afr[4][4];
#pragma unroll
        for (int m = 0; m < 4; m++)
            ldmat_x4(afr[m], aAddr + m * 16 * (WPITCH * 2) + k0 * 2);
        uint32_t bfr[4][2];
#pragma unroll
        for (int j = 0; j < 4; j++)
            ldmat_x2(bfr[j], bAddr + j * 8 * (WPITCH * 2) + k0 * 2);
#pragma unroll
        for (int m = 0; m < 4; m++)
#pragma unroll
            for (int j = 0; j < 4; j++)
                mma_16816(acc[m][j], afr[m], bfr[j]);
    }

    // ---- Epilogue: bn2 + store ----
    {
        const int ncol = n0 + nw + (lane & 3) * 2;
#pragma unroll
        for (int m = 0; m < 4; m++) {
            const int r0 = ow + m * 16 + (lane >> 2);
            const int r1 = r0 + 8;
            const float2 s0 = __ldg(&g_bn2[r0]);
            const float2 s1 = __ldg(&g_bn2[r1]);
            float* p0 = out + ((size_t)(b * OO + r0)) * HWN + ncol;
            float* p1 = out + ((size_t)(b * OO + r1)) * HWN + ncol;
#pragma unroll
            for (int j = 0; j < 4; j++) {
                float2 v0, v1;
                v0.x = fmaf(acc[m][j][0], s0.x, s0.y);
                v0.y = fmaf(acc[m][j][1], s0.x, s0.y);
                v1.x = fmaf(acc[m][j][2], s1.x, s1.y);
                v1.y = fmaf(acc[m][j][3], s1.x, s1.y);
                *(float2*)(p0 + j * 8) = v0;
                *(float2*)(p1 + j * 8) = v1;
            }
        }
    }
}

// ---------------------------------------------------------------------------
// Persistent mega-kernel: queue-driven attn phase, then queue-driven fused
// phase with per-batch readiness flags. Deadlock-free: all items come from
// global atomic queues, so any resident CTA set makes progress.
// ---------------------------------------------------------------------------
__global__ __launch_bounds__(256, 2) void mega_kernel(
    const float* __restrict__ x,
    const float* __restrict__ aw,
    const float* __restrict__ bn1_g, const float* __restrict__ bn1_b,
    const float* __restrict__ bn1_m, const float* __restrict__ bn1_v,
    float* __restrict__ out)
{
    __shared__ __align__(16) __half Wsm[OO * WPITCH];   // 36864 B
    __shared__ __align__(16) __half Ysm[64 * WPITCH];   //  9216 B
    __shared__ float red[9][8];
    __shared__ float fin[9];
    __shared__ unsigned s_item;

    const int t = threadIdx.x;

    // ---- one-time W copy to smem (reused by all fused items of this CTA) ----
    {
        const float4* src = (const float4*)g_Whalf;
        float4* dst = (float4*)Wsm;
#pragma unroll
        for (int i = 0; i < 9; i++)
            dst[i * 256 + t] = __ldg(src + i * 256 + t);
    }

    // ---- attn phase (work queue) ----
    for (;;) {
        if (t == 0) s_item = atomicAdd(&g_qa, 1u);
        __syncthreads();
        const unsigned it = s_item;
        __syncthreads();
        if (it >= N_ATTN_ITEMS) break;
        do_attn_item((int)it, x, aw, bn1_g, bn1_b, bn1_m, bn1_v, red, fin);
    }

    // ---- fused phase (work queue) ----
    for (;;) {
        if (t == 0) s_item = atomicAdd(&g_qf, 1u);
        __syncthreads();
        const unsigned it = s_item;
        __syncthreads();
        if (it >= N_FUSED_ITEMS) break;
        do_fused_item((int)it, x, out, Wsm, Ysm);
    }
}

extern "C" void kernel_launch(void* const* d_in, const int* in_sizes, int n_in,
                              void* d_out, int out_size)
{
    const float* x     = (const float*)d_in[0];
    const float* aw    = (const float*)d_in[1];
    const float* bn1_g = (const float*)d_in[2];
    const float* bn1_b = (const float*)d_in[3];
    const float* bn1_m = (const float*)d_in[4];
    const float* bn1_v = (const float*)d_in[5];
    const float* convw = (const float*)d_in[6];
    const float* bn2_g = (const float*)d_in[7];
    const float* bn2_b = (const float*)d_in[8];
    const float* bn2_m = (const float*)d_in[9];
    const float* bn2_v = (const float*)d_in[10];
    float* out = (float*)d_out;

    prep_kernel<<<64, 256>>>(convw, bn2_g, bn2_b, bn2_m, bn2_v);
    mega_kernel<<<GRID_MEGA, 256>>>(x, aw, bn1_g, bn1_b, bn1_m, bn1_v, out);
}

// round 7
// speedup vs baseline: 1.1578x; 1.1578x over previous
#include <cuda_runtime.h>
#include <cuda_fp16.h>
#include <cstdint>

// Problem constants (fixed shapes)
#define BB 8
#define GG 64
#define CC 192
#define HWN 65536          // H*W
#define OO 256             // width2

#define WPITCH 72          // fp16 elements per row (144B): conflict-free ldmatrix

// ---------------------------------------------------------------------------
// Device scratch
// ---------------------------------------------------------------------------
__device__ float4 g_attnW[BB * GG];
__device__ __align__(16) __half g_Whalf[OO * WPITCH];
__device__ float2 g_bn2[OO];

__device__ __forceinline__ uint32_t smem_u32(const void* p) {
    uint32_t a;
    asm("{ .reg .u64 t; cvta.to.shared.u64 t, %1; cvt.u32.u64 %0, t; }" : "=r"(a) : "l"(p));
    return a;
}
__device__ __forceinline__ void ldmat_x4(uint32_t* r, uint32_t addr) {
    asm volatile("ldmatrix.sync.aligned.m8n8.x4.shared.b16 {%0,%1,%2,%3}, [%4];"
                 : "=r"(r[0]), "=r"(r[1]), "=r"(r[2]), "=r"(r[3]) : "r"(addr));
}
__device__ __forceinline__ void ldmat_x4_trans(uint32_t* r, uint32_t addr) {
    asm volatile("ldmatrix.sync.aligned.m8n8.x4.trans.shared.b16 {%0,%1,%2,%3}, [%4];"
                 : "=r"(r[0]), "=r"(r[1]), "=r"(r[2]), "=r"(r[3]) : "r"(addr));
}
__device__ __forceinline__ void mma_16816(float* d, const uint32_t* a, const uint32_t* b) {
    asm volatile("mma.sync.aligned.m16n8k16.row.col.f32.f16.f16.f32 "
                 "{%0,%1,%2,%3}, {%4,%5,%6,%7}, {%8,%9}, {%0,%1,%2,%3};"
                 : "+f"(d[0]), "+f"(d[1]), "+f"(d[2]), "+f"(d[3])
                 : "r"(a[0]), "r"(a[1]), "r"(a[2]), "r"(a[3]), "r"(b[0]), "r"(b[1]));
}

// ---------------------------------------------------------------------------
// Kernel 0: prep — conv_w -> fp16 pitched tile, fold bn2.
// ---------------------------------------------------------------------------
__global__ __launch_bounds__(256) void prep_kernel(
    const float* __restrict__ convw,
    const float* __restrict__ bn2_g, const float* __restrict__ bn2_b,
    const float* __restrict__ bn2_m, const float* __restrict__ bn2_v)
{
    const int i = blockIdx.x * 256 + threadIdx.x;   // 0..16383
    const int k = i & 63;
    const int o = i >> 6;
    g_Whalf[o * WPITCH + k] = __float2half(convw[o * GG + k]);
    if (i < OO) {
#pragma unroll
        for (int z = 64; z < WPITCH; z++)
            g_Whalf[i * WPITCH + z] = __float2half(0.f);
        float sc = bn2_g[i] * rsqrtf(bn2_v[i] + 1e-5f);
        float bi = bn2_b[i] - sc * bn2_m[i];
        g_bn2[i] = make_float2(sc, bi);
    }
}

// ---------------------------------------------------------------------------
// Kernel 1: attention statistics (HBM-bound, ~62us).
// ---------------------------------------------------------------------------
__global__ __launch_bounds__(256) void attn_kernel(
    const float* __restrict__ x,
    const float* __restrict__ aw,
    const float* __restrict__ bn1_g, const float* __restrict__ bn1_b,
    const float* __restrict__ bn1_m, const float* __restrict__ bn1_v)
{
    const int bg = blockIdx.x;
    const int g  = bg & 63;
    const float* xb = x + (size_t)bg * 3 * HWN;

    const int t    = threadIdx.x;
    const int lane = t & 31;
    const int warp = t >> 5;

    float acc[9];
#pragma unroll
    for (int q = 0; q < 9; q++) acc[q] = 0.0f;

#pragma unroll 1
    for (int it = 0; it < 16; it++) {
        const int wIdx = it * 256 + t;
        const int wy = wIdx >> 6;
        const int wx = wIdx & 63;
        float m[3], s[3];
#pragma unroll
        for (int ch = 0; ch < 3; ch++) {
            const float4* pc = (const float4*)(xb + (size_t)ch * HWN + (wy * 4) * 256 + wx * 4);
            float4 r0 = __ldcs(pc);
            float4 r1 = __ldcs(pc + 64);
            float4 r2 = __ldcs(pc + 128);
            float4 r3 = __ldcs(pc + 192);
            float mx = fmaxf(fmaxf(fmaxf(r0.x, r0.y), fmaxf(r0.z, r0.w)),
                      fmaxf(fmaxf(fmaxf(r1.x, r1.y), fmaxf(r1.z, r1.w)),
                      fmaxf(fmaxf(fmaxf(r2.x, r2.y), fmaxf(r2.z, r2.w)),
                            fmaxf(fmaxf(r3.x, r3.y), fmaxf(r3.z, r3.w)))));
            float sm = (r0.x + r0.y + r0.z + r0.w) + (r1.x + r1.y + r1.z + r1.w)
                     + (r2.x + r2.y + r2.z + r2.w) + (r3.x + r3.y + r3.z + r3.w);
            m[ch] = mx;
            s[ch] = sm;
        }
#pragma unroll
        for (int i = 0; i < 3; i++)
#pragma unroll
            for (int j = 0; j < 3; j++)
                acc[i * 3 + j] += m[i] * s[j];
    }

    __shared__ float red[9][8];
    __shared__ float fin[9];
#pragma unroll
    for (int q = 0; q < 9; q++) {
        float v = acc[q];
#pragma unroll
        for (int off = 16; off > 0; off >>= 1)
            v += __shfl_xor_sync(0xFFFFFFFFu, v, off);
        if (lane == 0) red[q][warp] = v;
    }
    __syncthreads();
    if (t < 9) {
        float s = 0.0f;
#pragma unroll
        for (int w = 0; w < 8; w++) s += red[t][w];
        fin[t] = s;
    }
    __syncthreads();

    if (t == 0) {
        const float w0 = aw[g * 3 + 0], w1 = aw[g * 3 + 1], w2 = aw[g * 3 + 2];
        float r0 = (fin[0] * w0 + fin[3] * w1 + fin[6] * w2) * (1.0f / 1024.0f);
        float r1 = (fin[1] * w0 + fin[4] * w1 + fin[7] * w2) * (1.0f / 1024.0f);
        float r2 = (fin[2] * w0 + fin[5] * w1 + fin[8] * w2) * (1.0f / 1024.0f);
        float mx = fmaxf(r0, fmaxf(r1, r2));
        float e0 = __expf(r0 - mx), e1 = __expf(r1 - mx), e2 = __expf(r2 - mx);
        float inv = 1.0f / (e0 + e1 + e2);
        float sc = bn1_g[g] * rsqrtf(bn1_v[g] + 1e-5f);
        float cc = bn1_b[g] - sc * bn1_m[g];
        float4 o;
        o.x = sc * e0 * inv;
        o.y = sc * e1 * inv;
        o.z = sc * e2 * inv;
        o.w = cc;
        g_attnW[bg] = o;
    }
}

// ---------------------------------------------------------------------------
// Kernel 2: fused weighted-sum + bn1 + relu + 1x1 conv (HMMA) + bn2.
// CTA: 256 threads (8 warps), 2 CTAs/SM. Tile: 256 o x 64 n, K = 64.
// Phase A: float4 loads (12 LDG.128/thread), Y stored [k][n] fp16 (pitch 72),
//          one 8B smem store per (g, n-quad).
// Phase B: warp = 64o x 32n; A via ldmatrix.x4, B via ldmatrix.x4.trans.
// ---------------------------------------------------------------------------
__global__ __launch_bounds__(256, 2) void fused_kernel(
    const float* __restrict__ x,
    float* __restrict__ out)
{
    __shared__ __align__(16) __half Wsm[OO * WPITCH];   // 36864 B, [o][k]
    __shared__ __align__(16) __half Ysm[64 * WPITCH];   //  9216 B, [k][n]

    const int t    = threadIdx.x;
    const int lane = t & 31;
    const int wid  = t >> 5;
    const int b    = blockIdx.y;
    const int n0   = blockIdx.x * 64;

    // ---- W copy to smem (36864 B = 2304 float4) ----
    {
        const float4* src = (const float4*)g_Whalf;
        float4* dst = (float4*)Wsm;
#pragma unroll
        for (int i = 0; i < 9; i++)
            dst[i * 256 + t] = __ldg(src + i * 256 + t);
    }

    // ---- Phase A: Y = relu(bn1(sum_j a_j x_j)) -> fp16 smem [k][n] ----
    {
        const int quad = t & 15;            // n-quad: positions pos4..pos4+3
        const int gi   = t >> 4;            // 0..15
        const int pos4 = quad * 4;
        const float* xb = x + (size_t)b * CC * HWN + n0 + pos4;
        const float4* awb = g_attnW + b * GG;
#pragma unroll
        for (int it = 0; it < 4; it++) {
            const int g = it * 16 + gi;
            const float4 a = __ldg(awb + g);
            const float* p = xb + (size_t)(g * 3) * HWN;
            float4 x0 = __ldcs((const float4*)p);
            float4 x1 = __ldcs((const float4*)(p + HWN));
            float4 x2 = __ldcs((const float4*)(p + 2 * HWN));
            float y0 = fmaxf(fmaf(a.x, x0.x, fmaf(a.y, x1.x, fmaf(a.z, x2.x, a.w))), 0.0f);
            float y1 = fmaxf(fmaf(a.x, x0.y, fmaf(a.y, x1.y, fmaf(a.z, x2.y, a.w))), 0.0f);
            float y2 = fmaxf(fmaf(a.x, x0.z, fmaf(a.y, x1.z, fmaf(a.z, x2.z, a.w))), 0.0f);
            float y3 = fmaxf(fmaf(a.x, x0.w, fmaf(a.y, x1.w, fmaf(a.z, x2.w, a.w))), 0.0f);
            union { __half2 h[2]; uint2 u; } pk;
            pk.h[0] = __floats2half2_rn(y0, y1);
            pk.h[1] = __floats2half2_rn(y2, y3);
            *(uint2*)(Ysm + g * WPITCH + pos4) = pk.u;
        }
    }
    __syncthreads();

    // ---- Phase B: HMMA GEMM. warp tile: o in [ow, ow+64), n in [nw, nw+32) ----
    const int ow = (wid >> 1) * 64;
    const int nw = (wid & 1) * 32;

    float acc[4][4][4];
#pragma unroll
    for (int m = 0; m < 4; m++)
#pragma unroll
        for (int j = 0; j < 4; j++)
#pragma unroll
            for (int q = 0; q < 4; q++) acc[m][j][q] = 0.0f;

    const uint32_t wbase = smem_u32(Wsm);
    const uint32_t ybase = smem_u32(Ysm);
    // A (row-major o x k): lane -> row ow + m*16 + (lane&15), col chunk (lane>>4)*8
    const uint32_t aAddr = wbase + (ow + (lane & 15)) * (WPITCH * 2) + ((lane >> 4) * 8) * 2;
    // B trans from [k][n]: quadrant q=lane>>3, r=lane&7:
    //   row = (q&1)*8 + r (k), col = nw + (q>>1)*8 (n)
    const uint32_t brow = ((lane >> 3) & 1) * 8 + (lane & 7);
    const uint32_t bcol = nw + ((lane >> 4) * 8);
    const uint32_t bAddr = ybase + brow * (WPITCH * 2) + bcol * 2;

#pragma unroll
    for (int k0 = 0; k0 < 64; k0 += 16) {
        uint32_t afr[4][4];
#pragma unroll
        for (int m = 0; m < 4; m++)
            ldmat_x4(afr[m], aAddr + m * 16 * (WPITCH * 2) + k0 * 2);
        uint32_t bq0[4], bq1[4];   // n blocks {0,1} and {2,3}
        ldmat_x4_trans(bq0, bAddr + k0 * (WPITCH * 2));
        ldmat_x4_trans(bq1, bAddr + k0 * (WPITCH * 2) + 16 * 2);
        const uint32_t* bfr[4] = { &bq0[0], &bq0[2], &bq1[0], &bq1[2] };
#pragma unroll
        for (int m = 0; m < 4; m++)
#pragma unroll
            for (int j = 0; j < 4; j++)
                mma_16816(acc[m][j], afr[m], bfr[j]);
    }

    // ---- Epilogue: bn2 + store ----
    {
        const int ncol = n0 + nw + (lane & 3) * 2;
#pragma unroll
        for (int m = 0; m < 4; m++) {
            const int r0 = ow + m * 16 + (lane >> 2);
            const int r1 = r0 + 8;
            const float2 s0 = __ldg(&g_bn2[r0]);
            const float2 s1 = __ldg(&g_bn2[r1]);
            float* p0 = out + ((size_t)(b * OO + r0)) * HWN + ncol;
            float* p1 = out + ((size_t)(b * OO + r1)) * HWN + ncol;
#pragma unroll
            for (int j = 0; j < 4; j++) {
                float2 v0, v1;
                v0.x = fmaf(acc[m][j][0], s0.x, s0.y);
                v0.y = fmaf(acc[m][j][1], s0.x, s0.y);
                v1.x = fmaf(acc[m][j][2], s1.x, s1.y);
                v1.y = fmaf(acc[m][j][3], s1.x, s1.y);
                *(float2*)(p0 + j * 8) = v0;
                *(float2*)(p1 + j * 8) = v1;
            }
        }
    }
}

extern "C" void kernel_launch(void* const* d_in, const int* in_sizes, int n_in,
                              void* d_out, int out_size)
{
    const float* x     = (const float*)d_in[0];
    const float* aw    = (const float*)d_in[1];
    const float* bn1_g = (const float*)d_in[2];
    const float* bn1_b = (const float*)d_in[3];
    const float* bn1_m = (const float*)d_in[4];
    const float* bn1_v = (const float*)d_in[5];
    const float* convw = (const float*)d_in[6];
    const float* bn2_g = (const float*)d_in[7];
    const float* bn2_b = (const float*)d_in[8];
    const float* bn2_m = (const float*)d_in[9];
    const float* bn2_v = (const float*)d_in[10];
    float* out = (float*)d_out;

    prep_kernel<<<64, 256>>>(convw, bn2_g, bn2_b, bn2_m, bn2_v);
    attn_kernel<<<BB * GG, 256>>>(x, aw, bn1_g, bn1_b, bn1_m, bn1_v);
    fused_kernel<<<dim3(HWN / 64, BB), 256>>>(x, out);
}